// round 14
// baseline (speedup 1.0000x reference)
#include <cuda_runtime.h>
#include <cuda_fp16.h>
#include <cstdint>

#define NB 16
#define NC 512
#define NO 512
#define NH 64
#define NW 64

__device__ float g_wsq[NO * NC];
__device__ float g_siginv[NB * NO];
__device__ __half g_U[16 * NO * NC];                        // [t][o][i], c folded
__device__ __half g_V[(size_t)NB * 16 * 1024 * NC];         // [b][t][tile][i]
__device__ __half g_M[(size_t)NB * 16 * NO * 1024];         // [b][t][o][tile]

// ---------------- prepass: U = G g G^T (c folded) + wsq ----------------
__global__ void prep_u_kernel(const float* __restrict__ w) {
    int idx = blockIdx.x * blockDim.x + threadIdx.x;   // o*512 + i
    if (idx >= NO * NC) return;
    const float cc = rsqrtf((float)(NC * 9));
    const float* p = w + (size_t)idx * 9;
    float g[3][3];
    float sum = 0.f;
#pragma unroll
    for (int r = 0; r < 3; r++)
#pragma unroll
        for (int c = 0; c < 3; c++) {
            float v = p[r * 3 + c];
            sum += v * v;
            g[r][c] = v * cc;
        }
    g_wsq[idx] = sum;
    float ur[4][3];
#pragma unroll
    for (int c = 0; c < 3; c++) {
        ur[0][c] = g[0][c];
        ur[1][c] = 0.5f * (g[0][c] + g[1][c] + g[2][c]);
        ur[2][c] = 0.5f * (g[0][c] - g[1][c] + g[2][c]);
        ur[3][c] = g[2][c];
    }
#pragma unroll
    for (int k = 0; k < 4; k++) {
        float u0 = ur[k][0], u1 = ur[k][1], u2 = ur[k][2];
        g_U[((size_t)(k * 4 + 0) * NO * NC) + idx] = __float2half(u0);
        g_U[((size_t)(k * 4 + 1) * NO * NC) + idx] = __float2half(0.5f * (u0 + u1 + u2));
        g_U[((size_t)(k * 4 + 2) * NO * NC) + idx] = __float2half(0.5f * (u0 - u1 + u2));
        g_U[((size_t)(k * 4 + 3) * NO * NC) + idx] = __float2half(u2);
    }
}

__global__ void siginv_kernel(const float* __restrict__ s) {
    int gw = blockIdx.x * (blockDim.x >> 5) + (threadIdx.x >> 5);
    if (gw >= NB * NO) return;
    int b = gw >> 9, o = gw & 511, lane = threadIdx.x & 31;
    float sum = 0.f;
    for (int i = lane; i < NC; i += 32) {
        float sv = s[b * NC + i];
        sum += sv * sv * g_wsq[o * NC + i];
    }
#pragma unroll
    for (int off = 16; off > 0; off >>= 1)
        sum += __shfl_xor_sync(0xFFFFFFFFu, sum, off);
    if (lane == 0) g_siginv[gw] = rsqrtf(sum * (1.0f / (NC * 9)) + 1e-8f);
}

// ---------------- input transform: V = B^T d B,  d = xpad * s ----------------
__global__ void vtrans_kernel(const float* __restrict__ x, const float* __restrict__ s) {
    extern __shared__ float sd[];            // [4][64][68]
    __shared__ float ss[64];
    const int th = blockIdx.x, b = blockIdx.y;
    const int tid = threadIdx.x;
    const int warp = tid >> 5, L = tid & 31;

    for (int cb = 0; cb < 8; cb++) {
        __syncthreads();
        if (tid < 64) ss[tid] = s[b * NC + cb * 64 + tid];
        __syncthreads();
        for (int e = tid; e < 4 * 64 * 66; e += 256) {
            int r   = e / (64 * 66);
            int rem = e - r * (64 * 66);
            int ch  = rem / 66;
            int col = rem - ch * 66;
            int xr = 2 * th - 1 + r;
            int xc = col - 1;
            float v = 0.f;
            if (xr >= 0 && xr < NH && xc >= 0 && xc < NW)
                v = x[(((size_t)b * NC + cb * 64 + ch) * NH + xr) * NW + xc] * ss[ch];
            sd[(r * 64 + ch) * 68 + col] = v;
        }
        __syncthreads();
#pragma unroll
        for (int it = 0; it < 4; it++) {
            const int tw = warp + it * 8;
            float d0[4][4], d1[4][4];
#pragma unroll
            for (int r = 0; r < 4; r++)
#pragma unroll
                for (int c = 0; c < 4; c++) {
                    d0[r][c] = sd[(r * 64 + 2 * L) * 68 + 2 * tw + c];
                    d1[r][c] = sd[(r * 64 + 2 * L + 1) * 68 + 2 * tw + c];
                }
            float e0[4][4], e1[4][4];
#pragma unroll
            for (int c = 0; c < 4; c++) {
                e0[0][c] = d0[0][c] - d0[2][c];  e1[0][c] = d1[0][c] - d1[2][c];
                e0[1][c] = d0[1][c] + d0[2][c];  e1[1][c] = d1[1][c] + d1[2][c];
                e0[2][c] = d0[2][c] - d0[1][c];  e1[2][c] = d1[2][c] - d1[1][c];
                e0[3][c] = d0[1][c] - d0[3][c];  e1[3][c] = d1[1][c] - d1[3][c];
            }
            const size_t tilebase = ((size_t)(b * 16) * 1024 + th * 32 + tw) * NC
                                    + cb * 64 + 2 * L;
#pragma unroll
            for (int k = 0; k < 4; k++) {
                float v0[4], v1[4];
                v0[0] = e0[k][0] - e0[k][2];  v1[0] = e1[k][0] - e1[k][2];
                v0[1] = e0[k][1] + e0[k][2];  v1[1] = e1[k][1] + e1[k][2];
                v0[2] = e0[k][2] - e0[k][1];  v1[2] = e1[k][2] - e1[k][1];
                v0[3] = e0[k][1] - e0[k][3];  v1[3] = e1[k][1] - e1[k][3];
#pragma unroll
                for (int l = 0; l < 4; l++) {
                    const int t = k * 4 + l;
                    *reinterpret_cast<__half2*>(
                        &g_V[tilebase + (size_t)t * 1024 * NC]) =
                        __floats2half2_rn(v0[l], v1[l]);
                }
            }
        }
    }
}

// ---------------- GEMM: M[z][o][tile] = U[t] @ V[z], K-chunk=64 ----------------
#define PITCH 24                           // halves per smem row (48B)
#define ASLAB (128 * PITCH)                // per k16-group
#define BSLAB (256 * PITCH)
#define ASTG (4 * ASLAB)
#define BSTG (4 * BSLAB)
#define NSTAGE 3
#define SMEM_BYTES (NSTAGE * (ASTG + BSTG) * 2)   // 221184

#define CP16(dst, src) \
    asm volatile("cp.async.cg.shared.global [%0], [%1], 16;" :: "r"(dst), "l"(src))
#define CP_COMMIT() asm volatile("cp.async.commit_group;" ::: "memory")
#define LDMX4(r, a) asm volatile( \
    "ldmatrix.sync.aligned.m8n8.x4.shared.b16 {%0,%1,%2,%3}, [%4];" \
    : "=r"((r)[0]), "=r"((r)[1]), "=r"((r)[2]), "=r"((r)[3]) : "r"(a))

__device__ __forceinline__ void mma_fp16(float d[4], const uint32_t a[4],
                                         uint32_t b0, uint32_t b1) {
    asm volatile(
        "mma.sync.aligned.m16n8k16.row.col.f32.f16.f16.f32 "
        "{%0,%1,%2,%3}, {%4,%5,%6,%7}, {%8,%9}, {%0,%1,%2,%3};\n"
        : "+f"(d[0]), "+f"(d[1]), "+f"(d[2]), "+f"(d[3])
        : "r"(a[0]), "r"(a[1]), "r"(a[2]), "r"(a[3]), "r"(b0), "r"(b1));
}

__global__ void __launch_bounds__(256, 1)
wino_gemm_kernel() {
    extern __shared__ __half sm[];
    const int z  = blockIdx.z;             // b*16 + t
    const int t  = z & 15;
    const int o0 = blockIdx.y * 128;
    const int tile0 = blockIdx.x * 256;

    const int tid  = threadIdx.x;
    const int lane = tid & 31;
    const int warp = tid >> 5;
    const int wm = warp >> 2;              // 0..1 -> 64-o slab
    const int wn = warp & 3;               // 0..3 -> 64-tile slab
    const int g4 = lane >> 2;
    const int tg = lane & 3;

    uint32_t smbase;
    asm("{ .reg .u64 t; cvta.to.shared.u64 t, %1; cvt.u32.u64 %0, t; }"
        : "=r"(smbase) : "l"((const void*)sm));
    const uint32_t STG = (uint32_t)((ASTG + BSTG) * 2);

    const int lg = lane >> 3, lr = lane & 7;
    const uint32_t a_lane = (uint32_t)((wm * 64 + (lg & 1) * 8 + lr) * (PITCH * 2)
                                       + (lg >> 1) * 16);
    const uint32_t b_lane = (uint32_t)((((lg >> 1) * 8) + lr) * (PITCH * 2)
                                       + (lg & 1) * 16);

    float acc[4][8][4];
#pragma unroll
    for (int mt = 0; mt < 4; mt++)
#pragma unroll
        for (int nt = 0; nt < 8; nt++)
#pragma unroll
            for (int q = 0; q < 4; q++) acc[mt][nt][q] = 0.f;

    const __half* usrc = g_U + ((size_t)t * NO + o0) * NC;
    const __half* vsrc = g_V + ((size_t)z * 1024 + tile0) * NC;

    // LANE-MINOR piece indexing: each warp cp.async covers 4 rows x 128B
    // contiguous gmem (4 L1tex lines, not 32).
    auto load_chunk = [&](int c, int stg) {
        const uint32_t Ad = smbase + stg * STG;
        const uint32_t Bd = Ad + ASTG * 2;
#pragma unroll 4
        for (int e = tid; e < 1024; e += 256) {   // A: 128 rows x 8 pieces
            int row = e >> 3, p = e & 7;
            int k16 = p >> 1, h = p & 1;
            CP16(Ad + (uint32_t)(k16 * ASLAB * 2 + row * (PITCH * 2) + h * 16),
                 usrc + (size_t)row * NC + c * 64 + p * 8);
        }
#pragma unroll 8
        for (int e = tid; e < 2048; e += 256) {   // B: 256 rows x 8 pieces
            int row = e >> 3, p = e & 7;
            int k16 = p >> 1, h = p & 1;
            CP16(Bd + (uint32_t)(k16 * BSLAB * 2 + row * (PITCH * 2) + h * 16),
                 vsrc + (size_t)row * NC + c * 64 + p * 8);
        }
        CP_COMMIT();
    };

    load_chunk(0, 0);
    load_chunk(1, 1);

    for (int c = 0; c < 8; c++) {
        const int stg = c % NSTAGE;
        if (c + 2 < 8)
            asm volatile("cp.async.wait_group 1;" ::: "memory");
        else
            asm volatile("cp.async.wait_group 0;" ::: "memory");
        __syncthreads();
        if (c + 2 < 8) load_chunk(c + 2, (c + 2) % NSTAGE);

        const uint32_t Abuf = smbase + stg * STG;
        const uint32_t Bbuf = Abuf + ASTG * 2;
#pragma unroll
        for (int k16 = 0; k16 < 4; k16++) {
            uint32_t a[4][4];
#pragma unroll
            for (int mt = 0; mt < 4; mt++)
                LDMX4(a[mt], Abuf + (uint32_t)(k16 * ASLAB * 2
                             + (mt * 16) * (PITCH * 2)) + a_lane);
            const uint32_t brow = Bbuf + (uint32_t)(k16 * BSLAB * 2
                                  + (wn * 64) * (PITCH * 2)) + b_lane;
#pragma unroll
            for (int np = 0; np < 4; np++) {
                uint32_t bb[4];
                LDMX4(bb, brow + (uint32_t)(np * 16 * (PITCH * 2)));
#pragma unroll
                for (int mt = 0; mt < 4; mt++)
                    mma_fp16(acc[mt][2 * np], a[mt], bb[0], bb[1]);
#pragma unroll
                for (int mt = 0; mt < 4; mt++)
                    mma_fp16(acc[mt][2 * np + 1], a[mt], bb[2], bb[3]);
            }
        }
    }

    // epilogue: write M fp16
    __half* mbase = g_M + ((size_t)z * NO) * 1024;
#pragma unroll
    for (int mt = 0; mt < 4; mt++) {
        const int o_r = o0 + wm * 64 + mt * 16 + g4;
#pragma unroll
        for (int nt = 0; nt < 8; nt++) {
            const int tile = tile0 + wn * 64 + nt * 8 + tg * 2;
            *reinterpret_cast<__half2*>(&mbase[(size_t)o_r * 1024 + tile]) =
                __floats2half2_rn(acc[mt][nt][0], acc[mt][nt][1]);
            *reinterpret_cast<__half2*>(&mbase[(size_t)(o_r + 8) * 1024 + tile]) =
                __floats2half2_rn(acc[mt][nt][2], acc[mt][nt][3]);
        }
    }
}

// ---------------- output transform: Y = A^T m A, x siginv (vectorized) ----------------
__global__ void otrans_kernel(float* __restrict__ out) {
    const int o = blockIdx.x, b = blockIdx.y;
    const int tid = threadIdx.x;
    const float sc = g_siginv[b * NO + o];
    const __half* mb = g_M + ((size_t)(b * 16) * NO + o) * 1024;
    float* ob = out + ((size_t)b * NO + o) * NH * NW;
    const size_t tstride = (size_t)NO * 1024;

#pragma unroll
    for (int k = 0; k < 2; k++) {
        const int idx = k * 256 + tid;      // tile-pair index 0..511
        const int tile = 2 * idx;
        float mA[16], mB[16];
#pragma unroll
        for (int t = 0; t < 16; t++) {
            float2 v = __half22float2(
                *reinterpret_cast<const __half2*>(&mb[(size_t)t * tstride + tile]));
            mA[t] = v.x; mB[t] = v.y;
        }
        float fA0[4], fA1[4], fB0[4], fB1[4];
#pragma unroll
        for (int c = 0; c < 4; c++) {
            fA0[c] = mA[c] + mA[4 + c] + mA[8 + c];
            fA1[c] = mA[4 + c] - mA[8 + c] - mA[12 + c];
            fB0[c] = mB[c] + mB[4 + c] + mB[8 + c];
            fB1[c] = mB[4 + c] - mB[8 + c] - mB[12 + c];
        }
        const int th = tile >> 5, tw = tile & 31;     // tw even
        float4 r0, r1;
        r0.x = (fA0[0] + fA0[1] + fA0[2]) * sc;
        r0.y = (fA0[1] - fA0[2] - fA0[3]) * sc;
        r0.z = (fB0[0] + fB0[1] + fB0[2]) * sc;
        r0.w = (fB0[1] - fB0[2] - fB0[3]) * sc;
        r1.x = (fA1[0] + fA1[1] + fA1[2]) * sc;
        r1.y = (fA1[1] - fA1[2] - fA1[3]) * sc;
        r1.z = (fB1[0] + fB1[1] + fB1[2]) * sc;
        r1.w = (fB1[1] - fB1[2] - fB1[3]) * sc;
        *reinterpret_cast<float4*>(&ob[(2 * th) * NW + 2 * tw]) = r0;
        *reinterpret_cast<float4*>(&ob[(2 * th + 1) * NW + 2 * tw]) = r1;
    }
}

// ---------------------------------------------------------------------------
extern "C" void kernel_launch(void* const* d_in, const int* in_sizes, int n_in,
                              void* d_out, int out_size) {
    const float* x = (const float*)d_in[0];
    const float* s = (const float*)d_in[1];
    const float* w = (const float*)d_in[2];
    float* out = (float*)d_out;
    (void)in_sizes; (void)n_in; (void)out_size;

    prep_u_kernel<<<(NO * NC + 255) / 256, 256>>>(w);
    siginv_kernel<<<(NB * NO) / 8, 256>>>(s);

    const int vsmem = 4 * 64 * 68 * 4;   // 69632
    cudaFuncSetAttribute(vtrans_kernel,
                         cudaFuncAttributeMaxDynamicSharedMemorySize, vsmem);
    dim3 vg(32, NB);
    vtrans_kernel<<<vg, 256, vsmem>>>(x, s);

    cudaFuncSetAttribute(wino_gemm_kernel,
                         cudaFuncAttributeMaxDynamicSharedMemorySize, SMEM_BYTES);
    dim3 gg(4, 4, NB * 16);
    wino_gemm_kernel<<<gg, 256, SMEM_BYTES>>>();

    dim3 og(NO, NB);
    otrans_kernel<<<og, 256>>>(out);
}

// round 15
// speedup vs baseline: 1.0431x; 1.0431x over previous
#include <cuda_runtime.h>
#include <cuda_fp16.h>
#include <cstdint>

#define NB 16
#define NC 512
#define NO 512
#define NH 64
#define NW 64

__device__ float g_wsq[NO * NC];
__device__ float g_siginv[NB * NO];
__device__ __half g_U[16 * NO * NC];                        // [t][o][i], c folded
__device__ __half g_V[(size_t)NB * 16 * 1024 * NC];         // [b][t][tile][i]
__device__ __half g_M[(size_t)NB * 16 * NO * 1024];         // [b][t][o][tile]

// ---------------- prepass: U = G g G^T (c folded) + wsq ----------------
__global__ void prep_u_kernel(const float* __restrict__ w) {
    int idx = blockIdx.x * blockDim.x + threadIdx.x;   // o*512 + i
    if (idx >= NO * NC) return;
    const float cc = rsqrtf((float)(NC * 9));
    const float* p = w + (size_t)idx * 9;
    float g[3][3];
    float sum = 0.f;
#pragma unroll
    for (int r = 0; r < 3; r++)
#pragma unroll
        for (int c = 0; c < 3; c++) {
            float v = p[r * 3 + c];
            sum += v * v;
            g[r][c] = v * cc;
        }
    g_wsq[idx] = sum;
    float ur[4][3];
#pragma unroll
    for (int c = 0; c < 3; c++) {
        ur[0][c] = g[0][c];
        ur[1][c] = 0.5f * (g[0][c] + g[1][c] + g[2][c]);
        ur[2][c] = 0.5f * (g[0][c] - g[1][c] + g[2][c]);
        ur[3][c] = g[2][c];
    }
#pragma unroll
    for (int k = 0; k < 4; k++) {
        float u0 = ur[k][0], u1 = ur[k][1], u2 = ur[k][2];
        g_U[((size_t)(k * 4 + 0) * NO * NC) + idx] = __float2half(u0);
        g_U[((size_t)(k * 4 + 1) * NO * NC) + idx] = __float2half(0.5f * (u0 + u1 + u2));
        g_U[((size_t)(k * 4 + 2) * NO * NC) + idx] = __float2half(0.5f * (u0 - u1 + u2));
        g_U[((size_t)(k * 4 + 3) * NO * NC) + idx] = __float2half(u2);
    }
}

__global__ void siginv_kernel(const float* __restrict__ s) {
    int gw = blockIdx.x * (blockDim.x >> 5) + (threadIdx.x >> 5);
    if (gw >= NB * NO) return;
    int b = gw >> 9, o = gw & 511, lane = threadIdx.x & 31;
    float sum = 0.f;
    for (int i = lane; i < NC; i += 32) {
        float sv = s[b * NC + i];
        sum += sv * sv * g_wsq[o * NC + i];
    }
#pragma unroll
    for (int off = 16; off > 0; off >>= 1)
        sum += __shfl_xor_sync(0xFFFFFFFFu, sum, off);
    if (lane == 0) g_siginv[gw] = rsqrtf(sum * (1.0f / (NC * 9)) + 1e-8f);
}

// ---------------- input transform: V = B^T d B,  d = xpad * s ----------------
__global__ void vtrans_kernel(const float* __restrict__ x, const float* __restrict__ s) {
    extern __shared__ float sd[];            // [4][64][68]
    __shared__ float ss[64];
    const int th = blockIdx.x, b = blockIdx.y;
    const int tid = threadIdx.x;
    const int warp = tid >> 5, L = tid & 31;

    for (int cb = 0; cb < 8; cb++) {
        __syncthreads();
        if (tid < 64) ss[tid] = s[b * NC + cb * 64 + tid];
        __syncthreads();
        for (int e = tid; e < 4 * 64 * 66; e += 256) {
            int r   = e / (64 * 66);
            int rem = e - r * (64 * 66);
            int ch  = rem / 66;
            int col = rem - ch * 66;
            int xr = 2 * th - 1 + r;
            int xc = col - 1;
            float v = 0.f;
            if (xr >= 0 && xr < NH && xc >= 0 && xc < NW)
                v = x[(((size_t)b * NC + cb * 64 + ch) * NH + xr) * NW + xc] * ss[ch];
            sd[(r * 64 + ch) * 68 + col] = v;
        }
        __syncthreads();
#pragma unroll
        for (int it = 0; it < 4; it++) {
            const int tw = warp + it * 8;
            float d0[4][4], d1[4][4];
#pragma unroll
            for (int r = 0; r < 4; r++)
#pragma unroll
                for (int c = 0; c < 4; c++) {
                    d0[r][c] = sd[(r * 64 + 2 * L) * 68 + 2 * tw + c];
                    d1[r][c] = sd[(r * 64 + 2 * L + 1) * 68 + 2 * tw + c];
                }
            float e0[4][4], e1[4][4];
#pragma unroll
            for (int c = 0; c < 4; c++) {
                e0[0][c] = d0[0][c] - d0[2][c];  e1[0][c] = d1[0][c] - d1[2][c];
                e0[1][c] = d0[1][c] + d0[2][c];  e1[1][c] = d1[1][c] + d1[2][c];
                e0[2][c] = d0[2][c] - d0[1][c];  e1[2][c] = d1[2][c] - d1[1][c];
                e0[3][c] = d0[1][c] - d0[3][c];  e1[3][c] = d1[1][c] - d1[3][c];
            }
            const size_t tilebase = ((size_t)(b * 16) * 1024 + th * 32 + tw) * NC
                                    + cb * 64 + 2 * L;
#pragma unroll
            for (int k = 0; k < 4; k++) {
                float v0[4], v1[4];
                v0[0] = e0[k][0] - e0[k][2];  v1[0] = e1[k][0] - e1[k][2];
                v0[1] = e0[k][1] + e0[k][2];  v1[1] = e1[k][1] + e1[k][2];
                v0[2] = e0[k][2] - e0[k][1];  v1[2] = e1[k][2] - e1[k][1];
                v0[3] = e0[k][1] - e0[k][3];  v1[3] = e1[k][1] - e1[k][3];
#pragma unroll
                for (int l = 0; l < 4; l++) {
                    const int t = k * 4 + l;
                    *reinterpret_cast<__half2*>(
                        &g_V[tilebase + (size_t)t * 1024 * NC]) =
                        __floats2half2_rn(v0[l], v1[l]);
                }
            }
        }
    }
}

// ---------------- GEMM: M[z][o][tile] = U[t] @ V[z], 512 threads ----------------
#define PITCH 24                           // halves per smem row (48B)
#define ASLAB (128 * PITCH)                // per k16-group
#define BSLAB (256 * PITCH)
#define ASTG (4 * ASLAB)
#define BSTG (4 * BSLAB)
#define NSTAGE 3
#define SMEM_BYTES (NSTAGE * (ASTG + BSTG) * 2)   // 221184

#define CP16(dst, src) \
    asm volatile("cp.async.cg.shared.global [%0], [%1], 16;" :: "r"(dst), "l"(src))
#define CP_COMMIT() asm volatile("cp.async.commit_group;" ::: "memory")
#define LDMX4(r, a) asm volatile( \
    "ldmatrix.sync.aligned.m8n8.x4.shared.b16 {%0,%1,%2,%3}, [%4];" \
    : "=r"((r)[0]), "=r"((r)[1]), "=r"((r)[2]), "=r"((r)[3]) : "r"(a))

__device__ __forceinline__ void mma_fp16(float d[4], const uint32_t a[4],
                                         uint32_t b0, uint32_t b1) {
    asm volatile(
        "mma.sync.aligned.m16n8k16.row.col.f32.f16.f16.f32 "
        "{%0,%1,%2,%3}, {%4,%5,%6,%7}, {%8,%9}, {%0,%1,%2,%3};\n"
        : "+f"(d[0]), "+f"(d[1]), "+f"(d[2]), "+f"(d[3])
        : "r"(a[0]), "r"(a[1]), "r"(a[2]), "r"(a[3]), "r"(b0), "r"(b1));
}

__global__ void __launch_bounds__(512, 1)
wino_gemm_kernel() {
    extern __shared__ __half sm[];
    const int z  = blockIdx.z;             // b*16 + t
    const int t  = z & 15;
    const int o0 = blockIdx.y * 128;
    const int tile0 = blockIdx.x * 256;

    const int tid  = threadIdx.x;
    const int lane = tid & 31;
    const int warp = tid >> 5;             // 0..15
    const int wm = warp >> 2;              // 0..3 -> 32-o slab
    const int wn = warp & 3;               // 0..3 -> 64-tile slab
    const int g4 = lane >> 2;
    const int tg = lane & 3;

    uint32_t smbase;
    asm("{ .reg .u64 t; cvta.to.shared.u64 t, %1; cvt.u32.u64 %0, t; }"
        : "=r"(smbase) : "l"((const void*)sm));
    const uint32_t STG = (uint32_t)((ASTG + BSTG) * 2);

    const int lg = lane >> 3, lr = lane & 7;
    const uint32_t a_lane = (uint32_t)((wm * 32 + (lg & 1) * 8 + lr) * (PITCH * 2)
                                       + (lg >> 1) * 16);
    const uint32_t b_lane = (uint32_t)((((lg >> 1) * 8) + lr) * (PITCH * 2)
                                       + (lg & 1) * 16);

    float acc[2][8][4];
#pragma unroll
    for (int mt = 0; mt < 2; mt++)
#pragma unroll
        for (int nt = 0; nt < 8; nt++)
#pragma unroll
            for (int q = 0; q < 4; q++) acc[mt][nt][q] = 0.f;

    const __half* usrc = g_U + ((size_t)t * NO + o0) * NC;
    const __half* vsrc = g_V + ((size_t)z * 1024 + tile0) * NC;

    auto load_chunk = [&](int c, int stg) {
        const uint32_t Ad = smbase + stg * STG;
        const uint32_t Bd = Ad + ASTG * 2;
#pragma unroll 2
        for (int e = tid; e < 1024; e += 512) {   // A: 128 rows x 8 pieces
            int row = e >> 3, p = e & 7;
            int k16 = p >> 1, h = p & 1;
            CP16(Ad + (uint32_t)(k16 * ASLAB * 2 + row * (PITCH * 2) + h * 16),
                 usrc + (size_t)row * NC + c * 64 + p * 8);
        }
#pragma unroll 4
        for (int e = tid; e < 2048; e += 512) {   // B: 256 rows x 8 pieces
            int row = e >> 3, p = e & 7;
            int k16 = p >> 1, h = p & 1;
            CP16(Bd + (uint32_t)(k16 * BSLAB * 2 + row * (PITCH * 2) + h * 16),
                 vsrc + (size_t)row * NC + c * 64 + p * 8);
        }
        CP_COMMIT();
    };

    load_chunk(0, 0);
    load_chunk(1, 1);

    for (int c = 0; c < 8; c++) {
        const int stg = c % NSTAGE;
        if (c + 2 < 8)
            asm volatile("cp.async.wait_group 1;" ::: "memory");
        else
            asm volatile("cp.async.wait_group 0;" ::: "memory");
        __syncthreads();
        if (c + 2 < 8) load_chunk(c + 2, (c + 2) % NSTAGE);

        const uint32_t Abuf = smbase + stg * STG;
        const uint32_t Bbuf = Abuf + ASTG * 2;
#pragma unroll
        for (int k16 = 0; k16 < 4; k16++) {
            uint32_t a[2][4];
#pragma unroll
            for (int mt = 0; mt < 2; mt++)
                LDMX4(a[mt], Abuf + (uint32_t)(k16 * ASLAB * 2
                             + (mt * 16) * (PITCH * 2)) + a_lane);
            const uint32_t brow = Bbuf + (uint32_t)(k16 * BSLAB * 2
                                  + (wn * 64) * (PITCH * 2)) + b_lane;
#pragma unroll
            for (int np = 0; np < 4; np++) {
                uint32_t bb[4];
                LDMX4(bb, brow + (uint32_t)(np * 16 * (PITCH * 2)));
                mma_fp16(acc[0][2 * np], a[0], bb[0], bb[1]);
                mma_fp16(acc[1][2 * np], a[1], bb[0], bb[1]);
                mma_fp16(acc[0][2 * np + 1], a[0], bb[2], bb[3]);
                mma_fp16(acc[1][2 * np + 1], a[1], bb[2], bb[3]);
            }
        }
    }

    // epilogue: write M fp16
    __half* mbase = g_M + ((size_t)z * NO) * 1024;
#pragma unroll
    for (int mt = 0; mt < 2; mt++) {
        const int o_r = o0 + wm * 32 + mt * 16 + g4;
#pragma unroll
        for (int nt = 0; nt < 8; nt++) {
            const int tile = tile0 + wn * 64 + nt * 8 + tg * 2;
            *reinterpret_cast<__half2*>(&mbase[(size_t)o_r * 1024 + tile]) =
                __floats2half2_rn(acc[mt][nt][0], acc[mt][nt][1]);
            *reinterpret_cast<__half2*>(&mbase[(size_t)(o_r + 8) * 1024 + tile]) =
                __floats2half2_rn(acc[mt][nt][2], acc[mt][nt][3]);
        }
    }
}

// ---------------- output transform: Y = A^T m A, x siginv (vectorized) ----------------
__global__ void otrans_kernel(float* __restrict__ out) {
    const int o = blockIdx.x, b = blockIdx.y;
    const int tid = threadIdx.x;
    const float sc = g_siginv[b * NO + o];
    const __half* mb = g_M + ((size_t)(b * 16) * NO + o) * 1024;
    float* ob = out + ((size_t)b * NO + o) * NH * NW;
    const size_t tstride = (size_t)NO * 1024;

#pragma unroll
    for (int k = 0; k < 2; k++) {
        const int idx = k * 256 + tid;      // tile-pair index 0..511
        const int tile = 2 * idx;
        float mA[16], mB[16];
#pragma unroll
        for (int t = 0; t < 16; t++) {
            float2 v = __half22float2(
                *reinterpret_cast<const __half2*>(&mb[(size_t)t * tstride + tile]));
            mA[t] = v.x; mB[t] = v.y;
        }
        float fA0[4], fA1[4], fB0[4], fB1[4];
#pragma unroll
        for (int c = 0; c < 4; c++) {
            fA0[c] = mA[c] + mA[4 + c] + mA[8 + c];
            fA1[c] = mA[4 + c] - mA[8 + c] - mA[12 + c];
            fB0[c] = mB[c] + mB[4 + c] + mB[8 + c];
            fB1[c] = mB[4 + c] - mB[8 + c] - mB[12 + c];
        }
        const int th = tile >> 5, tw = tile & 31;     // tw even
        float4 r0, r1;
        r0.x = (fA0[0] + fA0[1] + fA0[2]) * sc;
        r0.y = (fA0[1] - fA0[2] - fA0[3]) * sc;
        r0.z = (fB0[0] + fB0[1] + fB0[2]) * sc;
        r0.w = (fB0[1] - fB0[2] - fB0[3]) * sc;
        r1.x = (fA1[0] + fA1[1] + fA1[2]) * sc;
        r1.y = (fA1[1] - fA1[2] - fA1[3]) * sc;
        r1.z = (fB1[0] + fB1[1] + fB1[2]) * sc;
        r1.w = (fB1[1] - fB1[2] - fB1[3]) * sc;
        *reinterpret_cast<float4*>(&ob[(2 * th) * NW + 2 * tw]) = r0;
        *reinterpret_cast<float4*>(&ob[(2 * th + 1) * NW + 2 * tw]) = r1;
    }
}

// ---------------------------------------------------------------------------
extern "C" void kernel_launch(void* const* d_in, const int* in_sizes, int n_in,
                              void* d_out, int out_size) {
    const float* x = (const float*)d_in[0];
    const float* s = (const float*)d_in[1];
    const float* w = (const float*)d_in[2];
    float* out = (float*)d_out;
    (void)in_sizes; (void)n_in; (void)out_size;

    prep_u_kernel<<<(NO * NC + 255) / 256, 256>>>(w);
    siginv_kernel<<<(NB * NO) / 8, 256>>>(s);

    const int vsmem = 4 * 64 * 68 * 4;   // 69632
    cudaFuncSetAttribute(vtrans_kernel,
                         cudaFuncAttributeMaxDynamicSharedMemorySize, vsmem);
    dim3 vg(32, NB);
    vtrans_kernel<<<vg, 256, vsmem>>>(x, s);

    cudaFuncSetAttribute(wino_gemm_kernel,
                         cudaFuncAttributeMaxDynamicSharedMemorySize, SMEM_BYTES);
    dim3 gg(4, 4, NB * 16);
    wino_gemm_kernel<<<gg, 512, SMEM_BYTES>>>();

    dim3 og(NO, NB);
    otrans_kernel<<<og, 256>>>(out);
}

// round 16
// speedup vs baseline: 1.0612x; 1.0174x over previous
#include <cuda_runtime.h>
#include <cuda_fp16.h>
#include <cstdint>

#define NB 16
#define NC 512
#define NO 512
#define NH 64
#define NW 64

__device__ float g_wsq[NO * NC];
__device__ float g_siginv[NB * NO];
__device__ __half g_U[16 * NO * NC];                        // [t][o][i], c folded
__device__ __half g_V[(size_t)NB * 16 * 1024 * NC];         // [b][t][tile][i]
__device__ __half g_M[(size_t)NB * 16 * NO * 1024];         // [b][t][o][tile]

// ---------------- prepass: U = G g G^T (c folded) + wsq ----------------
__global__ void prep_u_kernel(const float* __restrict__ w) {
    int idx = blockIdx.x * blockDim.x + threadIdx.x;   // o*512 + i
    if (idx >= NO * NC) return;
    const float cc = rsqrtf((float)(NC * 9));
    const float* p = w + (size_t)idx * 9;
    float g[3][3];
    float sum = 0.f;
#pragma unroll
    for (int r = 0; r < 3; r++)
#pragma unroll
        for (int c = 0; c < 3; c++) {
            float v = p[r * 3 + c];
            sum += v * v;
            g[r][c] = v * cc;
        }
    g_wsq[idx] = sum;
    float ur[4][3];
#pragma unroll
    for (int c = 0; c < 3; c++) {
        ur[0][c] = g[0][c];
        ur[1][c] = 0.5f * (g[0][c] + g[1][c] + g[2][c]);
        ur[2][c] = 0.5f * (g[0][c] - g[1][c] + g[2][c]);
        ur[3][c] = g[2][c];
    }
#pragma unroll
    for (int k = 0; k < 4; k++) {
        float u0 = ur[k][0], u1 = ur[k][1], u2 = ur[k][2];
        g_U[((size_t)(k * 4 + 0) * NO * NC) + idx] = __float2half(u0);
        g_U[((size_t)(k * 4 + 1) * NO * NC) + idx] = __float2half(0.5f * (u0 + u1 + u2));
        g_U[((size_t)(k * 4 + 2) * NO * NC) + idx] = __float2half(0.5f * (u0 - u1 + u2));
        g_U[((size_t)(k * 4 + 3) * NO * NC) + idx] = __float2half(u2);
    }
}

__global__ void siginv_kernel(const float* __restrict__ s) {
    int gw = blockIdx.x * (blockDim.x >> 5) + (threadIdx.x >> 5);
    if (gw >= NB * NO) return;
    int b = gw >> 9, o = gw & 511, lane = threadIdx.x & 31;
    float sum = 0.f;
    for (int i = lane; i < NC; i += 32) {
        float sv = s[b * NC + i];
        sum += sv * sv * g_wsq[o * NC + i];
    }
#pragma unroll
    for (int off = 16; off > 0; off >>= 1)
        sum += __shfl_xor_sync(0xFFFFFFFFu, sum, off);
    if (lane == 0) g_siginv[gw] = rsqrtf(sum * (1.0f / (NC * 9)) + 1e-8f);
}

// ---------------- input transform: V = B^T d B,  d = xpad * s ----------------
// CTA covers 4 output rows (2 tile-row blocks), reading 6 x rows (1.5x overlap).
__global__ void vtrans_kernel(const float* __restrict__ x, const float* __restrict__ s) {
    extern __shared__ float sd[];            // [6][64][68]
    __shared__ float ss[64];
    const int th2 = blockIdx.x, b = blockIdx.y;   // th2: 0..15
    const int tid = threadIdx.x;
    const int warp = tid >> 5, L = tid & 31;

    for (int cb = 0; cb < 8; cb++) {
        __syncthreads();
        if (tid < 64) ss[tid] = s[b * NC + cb * 64 + tid];
        __syncthreads();
        // load 6 rows x 64 ch x 66 cols (x rows 4*th2-1 .. 4*th2+4)
        for (int e = tid; e < 6 * 64 * 66; e += 256) {
            int r   = e / (64 * 66);
            int rem = e - r * (64 * 66);
            int ch  = rem / 66;
            int col = rem - ch * 66;
            int xr = 4 * th2 - 1 + r;
            int xc = col - 1;
            float v = 0.f;
            if (xr >= 0 && xr < NH && xc >= 0 && xc < NW)
                v = x[(((size_t)b * NC + cb * 64 + ch) * NH + xr) * NW + xc] * ss[ch];
            sd[(r * 64 + ch) * 68 + col] = v;
        }
        __syncthreads();
#pragma unroll
        for (int sub = 0; sub < 2; sub++) {
            const int th = 2 * th2 + sub;
            const int r0 = 2 * sub;
#pragma unroll
            for (int it = 0; it < 4; it++) {
                const int tw = warp + it * 8;
                float d0[4][4], d1[4][4];
#pragma unroll
                for (int r = 0; r < 4; r++)
#pragma unroll
                    for (int c = 0; c < 4; c++) {
                        d0[r][c] = sd[((r0 + r) * 64 + 2 * L) * 68 + 2 * tw + c];
                        d1[r][c] = sd[((r0 + r) * 64 + 2 * L + 1) * 68 + 2 * tw + c];
                    }
                float e0[4][4], e1[4][4];
#pragma unroll
                for (int c = 0; c < 4; c++) {
                    e0[0][c] = d0[0][c] - d0[2][c];  e1[0][c] = d1[0][c] - d1[2][c];
                    e0[1][c] = d0[1][c] + d0[2][c];  e1[1][c] = d1[1][c] + d1[2][c];
                    e0[2][c] = d0[2][c] - d0[1][c];  e1[2][c] = d1[2][c] - d1[1][c];
                    e0[3][c] = d0[1][c] - d0[3][c];  e1[3][c] = d1[1][c] - d1[3][c];
                }
                const size_t tilebase = ((size_t)(b * 16) * 1024 + th * 32 + tw) * NC
                                        + cb * 64 + 2 * L;
#pragma unroll
                for (int k = 0; k < 4; k++) {
                    float v0[4], v1[4];
                    v0[0] = e0[k][0] - e0[k][2];  v1[0] = e1[k][0] - e1[k][2];
                    v0[1] = e0[k][1] + e0[k][2];  v1[1] = e1[k][1] + e1[k][2];
                    v0[2] = e0[k][2] - e0[k][1];  v1[2] = e1[k][2] - e1[k][1];
                    v0[3] = e0[k][1] - e0[k][3];  v1[3] = e1[k][1] - e1[k][3];
#pragma unroll
                    for (int l = 0; l < 4; l++) {
                        const int t = k * 4 + l;
                        *reinterpret_cast<__half2*>(
                            &g_V[tilebase + (size_t)t * 1024 * NC]) =
                            __floats2half2_rn(v0[l], v1[l]);
                    }
                }
            }
        }
    }
}

// ---------------- GEMM: M[z][o][tile] = U[t] @ V[z], 512 threads ----------------
#define PITCH 24                           // halves per smem row (48B)
#define ASLAB (128 * PITCH)                // per k16-group
#define BSLAB (256 * PITCH)
#define ASTG (4 * ASLAB)
#define BSTG (4 * BSLAB)
#define NSTAGE 3
#define SMEM_BYTES (NSTAGE * (ASTG + BSTG) * 2)   // 221184
#define ROWP 264                           // staged epilogue row pitch (halves)

#define CP16(dst, src) \
    asm volatile("cp.async.cg.shared.global [%0], [%1], 16;" :: "r"(dst), "l"(src))
#define CP_COMMIT() asm volatile("cp.async.commit_group;" ::: "memory")
#define LDMX4(r, a) asm volatile( \
    "ldmatrix.sync.aligned.m8n8.x4.shared.b16 {%0,%1,%2,%3}, [%4];" \
    : "=r"((r)[0]), "=r"((r)[1]), "=r"((r)[2]), "=r"((r)[3]) : "r"(a))

__device__ __forceinline__ void mma_fp16(float d[4], const uint32_t a[4],
                                         uint32_t b0, uint32_t b1) {
    asm volatile(
        "mma.sync.aligned.m16n8k16.row.col.f32.f16.f16.f32 "
        "{%0,%1,%2,%3}, {%4,%5,%6,%7}, {%8,%9}, {%0,%1,%2,%3};\n"
        : "+f"(d[0]), "+f"(d[1]), "+f"(d[2]), "+f"(d[3])
        : "r"(a[0]), "r"(a[1]), "r"(a[2]), "r"(a[3]), "r"(b0), "r"(b1));
}

__global__ void __launch_bounds__(512, 1)
wino_gemm_kernel() {
    extern __shared__ __half sm[];
    const int z  = blockIdx.z;             // b*16 + t
    const int t  = z & 15;
    const int o0 = blockIdx.y * 128;
    const int tile0 = blockIdx.x * 256;

    const int tid  = threadIdx.x;
    const int lane = tid & 31;
    const int warp = tid >> 5;             // 0..15
    const int wm = warp >> 2;              // 0..3 -> 32-o slab
    const int wn = warp & 3;               // 0..3 -> 64-tile slab
    const int g4 = lane >> 2;
    const int tg = lane & 3;

    uint32_t smbase;
    asm("{ .reg .u64 t; cvta.to.shared.u64 t, %1; cvt.u32.u64 %0, t; }"
        : "=r"(smbase) : "l"((const void*)sm));
    const uint32_t STG = (uint32_t)((ASTG + BSTG) * 2);

    const int lg = lane >> 3, lr = lane & 7;
    const uint32_t a_lane = (uint32_t)((wm * 32 + (lg & 1) * 8 + lr) * (PITCH * 2)
                                       + (lg >> 1) * 16);
    const uint32_t b_lane = (uint32_t)((((lg >> 1) * 8) + lr) * (PITCH * 2)
                                       + (lg & 1) * 16);

    float acc[2][8][4];
#pragma unroll
    for (int mt = 0; mt < 2; mt++)
#pragma unroll
        for (int nt = 0; nt < 8; nt++)
#pragma unroll
            for (int q = 0; q < 4; q++) acc[mt][nt][q] = 0.f;

    const __half* usrc = g_U + ((size_t)t * NO + o0) * NC;
    const __half* vsrc = g_V + ((size_t)z * 1024 + tile0) * NC;

    auto load_chunk = [&](int c, int stg) {
        const uint32_t Ad = smbase + stg * STG;
        const uint32_t Bd = Ad + ASTG * 2;
#pragma unroll 2
        for (int e = tid; e < 1024; e += 512) {   // A: 128 rows x 8 pieces
            int row = e >> 3, p = e & 7;
            int k16 = p >> 1, h = p & 1;
            CP16(Ad + (uint32_t)(k16 * ASLAB * 2 + row * (PITCH * 2) + h * 16),
                 usrc + (size_t)row * NC + c * 64 + p * 8);
        }
#pragma unroll 4
        for (int e = tid; e < 2048; e += 512) {   // B: 256 rows x 8 pieces
            int row = e >> 3, p = e & 7;
            int k16 = p >> 1, h = p & 1;
            CP16(Bd + (uint32_t)(k16 * BSLAB * 2 + row * (PITCH * 2) + h * 16),
                 vsrc + (size_t)row * NC + c * 64 + p * 8);
        }
        CP_COMMIT();
    };

    load_chunk(0, 0);
    load_chunk(1, 1);

    for (int c = 0; c < 8; c++) {
        const int stg = c % NSTAGE;
        if (c + 2 < 8)
            asm volatile("cp.async.wait_group 1;" ::: "memory");
        else
            asm volatile("cp.async.wait_group 0;" ::: "memory");
        __syncthreads();
        if (c + 2 < 8) load_chunk(c + 2, (c + 2) % NSTAGE);

        const uint32_t Abuf = smbase + stg * STG;
        const uint32_t Bbuf = Abuf + ASTG * 2;
#pragma unroll
        for (int k16 = 0; k16 < 4; k16++) {
            uint32_t a[2][4];
#pragma unroll
            for (int mt = 0; mt < 2; mt++)
                LDMX4(a[mt], Abuf + (uint32_t)(k16 * ASLAB * 2
                             + (mt * 16) * (PITCH * 2)) + a_lane);
            const uint32_t brow = Bbuf + (uint32_t)(k16 * BSLAB * 2
                                  + (wn * 64) * (PITCH * 2)) + b_lane;
#pragma unroll
            for (int np = 0; np < 4; np++) {
                uint32_t bb[4];
                LDMX4(bb, brow + (uint32_t)(np * 16 * (PITCH * 2)));
                mma_fp16(acc[0][2 * np], a[0], bb[0], bb[1]);
                mma_fp16(acc[1][2 * np], a[1], bb[0], bb[1]);
                mma_fp16(acc[0][2 * np + 1], a[0], bb[2], bb[3]);
                mma_fp16(acc[1][2 * np + 1], a[1], bb[2], bb[3]);
            }
        }
    }

    // ---- staged epilogue: acc -> smem (half) -> coalesced uint4 stores ----
    __syncthreads();                       // ring dead; safe to overwrite
#pragma unroll
    for (int mt = 0; mt < 2; mt++) {
        const int ol = wm * 32 + mt * 16 + g4;           // local o row
#pragma unroll
        for (int nt = 0; nt < 8; nt++) {
            const int tl = wn * 64 + nt * 8 + tg * 2;    // local tile
            *reinterpret_cast<__half2*>(&sm[ol * ROWP + tl]) =
                __floats2half2_rn(acc[mt][nt][0], acc[mt][nt][1]);
            *reinterpret_cast<__half2*>(&sm[(ol + 8) * ROWP + tl]) =
                __floats2half2_rn(acc[mt][nt][2], acc[mt][nt][3]);
        }
    }
    __syncthreads();
    __half* mbase = g_M + ((size_t)z * NO + o0) * 1024 + tile0;
#pragma unroll
    for (int e = tid; e < 128 * 32; e += 512) {
        const int row = e >> 5, seg = e & 31;            // 32 x 16B segs = 256 tiles
        *reinterpret_cast<uint4*>(mbase + (size_t)row * 1024 + seg * 8) =
            *reinterpret_cast<const uint4*>(sm + row * ROWP + seg * 8);
    }
}

// ---------------- output transform: Y = A^T m A, x siginv (vectorized) ----------------
__global__ void otrans_kernel(float* __restrict__ out) {
    const int o = blockIdx.x, b = blockIdx.y;
    const int tid = threadIdx.x;
    const float sc = g_siginv[b * NO + o];
    const __half* mb = g_M + ((size_t)(b * 16) * NO + o) * 1024;
    float* ob = out + ((size_t)b * NO + o) * NH * NW;
    const size_t tstride = (size_t)NO * 1024;

#pragma unroll
    for (int k = 0; k < 2; k++) {
        const int idx = k * 256 + tid;      // tile-pair index 0..511
        const int tile = 2 * idx;
        float mA[16], mB[16];
#pragma unroll
        for (int t = 0; t < 16; t++) {
            float2 v = __half22float2(
                *reinterpret_cast<const __half2*>(&mb[(size_t)t * tstride + tile]));
            mA[t] = v.x; mB[t] = v.y;
        }
        float fA0[4], fA1[4], fB0[4], fB1[4];
#pragma unroll
        for (int c = 0; c < 4; c++) {
            fA0[c] = mA[c] + mA[4 + c] + mA[8 + c];
            fA1[c] = mA[4 + c] - mA[8 + c] - mA[12 + c];
            fB0[c] = mB[c] + mB[4 + c] + mB[8 + c];
            fB1[c] = mB[4 + c] - mB[8 + c] - mB[12 + c];
        }
        const int th = tile >> 5, tw = tile & 31;     // tw even
        float4 r0, r1;
        r0.x = (fA0[0] + fA0[1] + fA0[2]) * sc;
        r0.y = (fA0[1] - fA0[2] - fA0[3]) * sc;
        r0.z = (fB0[0] + fB0[1] + fB0[2]) * sc;
        r0.w = (fB0[1] - fB0[2] - fB0[3]) * sc;
        r1.x = (fA1[0] + fA1[1] + fA1[2]) * sc;
        r1.y = (fA1[1] - fA1[2] - fA1[3]) * sc;
        r1.z = (fB1[0] + fB1[1] + fB1[2]) * sc;
        r1.w = (fB1[1] - fB1[2] - fB1[3]) * sc;
        *reinterpret_cast<float4*>(&ob[(2 * th) * NW + 2 * tw]) = r0;
        *reinterpret_cast<float4*>(&ob[(2 * th + 1) * NW + 2 * tw]) = r1;
    }
}

// ---------------------------------------------------------------------------
extern "C" void kernel_launch(void* const* d_in, const int* in_sizes, int n_in,
                              void* d_out, int out_size) {
    const float* x = (const float*)d_in[0];
    const float* s = (const float*)d_in[1];
    const float* w = (const float*)d_in[2];
    float* out = (float*)d_out;
    (void)in_sizes; (void)n_in; (void)out_size;

    prep_u_kernel<<<(NO * NC + 255) / 256, 256>>>(w);
    siginv_kernel<<<(NB * NO) / 8, 256>>>(s);

    const int vsmem = 6 * 64 * 68 * 4;   // 104448
    cudaFuncSetAttribute(vtrans_kernel,
                         cudaFuncAttributeMaxDynamicSharedMemorySize, vsmem);
    dim3 vg(16, NB);
    vtrans_kernel<<<vg, 256, vsmem>>>(x, s);

    cudaFuncSetAttribute(wino_gemm_kernel,
                         cudaFuncAttributeMaxDynamicSharedMemorySize, SMEM_BYTES);
    dim3 gg(4, 4, NB * 16);
    wino_gemm_kernel<<<gg, 512, SMEM_BYTES>>>();

    dim3 og(NO, NB);
    otrans_kernel<<<og, 256>>>(out);
}